// round 9
// baseline (speedup 1.0000x reference)
#include <cuda_runtime.h>
#include <cstdint>

// Problem constants
#define N_NODES 400
#define NM1     399                  // N_NODES - 1
#define E_EDGES (N_NODES * NM1)      // 159600
#define PAIRS   (E_EDGES / 2)        // 79800 float4 per batch image
#define QUADS   (PAIRS / 2)          // 39900 32-byte units per batch image
#define BATCH   32
#define BPT     8                    // batches per thread (sweep optimum)
#define BGROUPS (BATCH / BPT)        // grid.y = 4
#define THREADS 256
#define NBLKX   ((QUADS + THREADS - 1) / THREADS)   // 156

// Granularity experiment at the write-fabric roofline: identical byte volume
// and warp count to the 9.41us STG.128/BPT=8 config, but each thread now
// computes FOUR edges (32 B) and stores them with ONE st.global.v8.f32
// (STG.256) per batch slot — halving store-request count at constant payload.
// Discriminates per-request fabric overhead vs pure payload-byte ceiling.
__global__ __launch_bounds__(THREADS)
void nri_edge_onehot_v8_kernel(const float* __restrict__ adj,
                               float* __restrict__ out) {
    const int quad = blockIdx.x * THREADS + threadIdx.x;   // 0 .. QUADS-1
    if (quad >= QUADS) return;

    // Four consecutive edges e = 4*quad .. 4*quad+3
    float v[8];
    #pragma unroll
    for (int j = 0; j < 4; j++) {
        const int e = quad * 4 + j;
        // send = e / 399 ; k = e % 399 ; rec = k + (k >= send)
        const int s = e / NM1;
        const int k = e - s * NM1;
        const int r = k + (k >= s ? 1 : 0);
        const float a = __ldg(&adj[s * N_NODES + r]);
        const float t = (a != 0.0f) ? 1.0f : 0.0f;
        v[2 * j]     = 1.0f - t;
        v[2 * j + 1] = t;
    }

    // Broadcast to BPT batch slots with 256-bit stores (32B-aligned: quad*32).
    float* p = out + (size_t)(blockIdx.y * BPT) * (PAIRS * 4) + (size_t)quad * 8;
    #pragma unroll
    for (int b = 0; b < BPT; b++) {
        float* dst = p + (size_t)b * (PAIRS * 4);
        asm volatile(
            "st.global.v8.f32 [%0], {%1, %2, %3, %4, %5, %6, %7, %8};"
            :: "l"(dst),
               "f"(v[0]), "f"(v[1]), "f"(v[2]), "f"(v[3]),
               "f"(v[4]), "f"(v[5]), "f"(v[6]), "f"(v[7])
            : "memory");
    }
}

extern "C" void kernel_launch(void* const* d_in, const int* in_sizes, int n_in,
                              void* d_out, int out_size) {
    // Input order per reference setup_inputs():
    //   0: inputs  [32,400,12,1]   (unused)
    //   1: weather [32,12,4]       (unused)
    //   2: rel_rec [E,400]         (unused — indices recovered arithmetically)
    //   3: rel_send[E,400]         (unused)
    //   4: adj_matrix [400,400]    fp32
    const float* adj = (const float*)d_in[4];
    float* out = (float*)d_out;

    dim3 grid(NBLKX, BGROUPS);   // (156, 4)
    nri_edge_onehot_v8_kernel<<<grid, THREADS>>>(adj, out);
}